// round 14
// baseline (speedup 1.0000x reference)
#include <cuda_runtime.h>
#include <cstdint>

#define NN 8192
#define D 64
#define DO 128
#define K 16

#define SEGA 8
#define JSEGA 128
#define SEGB 14
#define JSEGB 512
#define JB0 1024
#define CAP 96
#define TJ 64

typedef unsigned long long u64;
typedef unsigned int u32;

// Scratch (module-scope device arrays; no runtime allocs)
__device__ float g_sq[NN];
__device__ float g_p[NN * DO];
__device__ float g_q[NN * DO];
__device__ u64 g_ck[NN * SEGA * K];
__device__ float g_thr[NN];
__device__ u64 g_cand[(size_t)NN * SEGB * CAP];
__device__ int g_cnt[NN * SEGB];
__device__ int g_nbr[NN * K];

// Packed fp32x2 math (FFMA2 path, PTX-only)
__device__ __forceinline__ u64 ffma2(u64 a, u64 b, u64 c) {
    u64 d;
    asm("fma.rn.f32x2 %0, %1, %2, %3;" : "=l"(d) : "l"(a), "l"(b), "l"(c));
    return d;
}
__device__ __forceinline__ u64 fadd2(u64 a, u64 b) {
    u64 d;
    asm("add.rn.f32x2 %0, %1, %2;" : "=l"(d) : "l"(a), "l"(b));
    return d;
}
__device__ __forceinline__ u32 fkey(float f) {
    u32 u = __float_as_uint(f);
    return (u & 0x80000000u) ? ~u : (u | 0x80000000u);
}
__device__ __forceinline__ float unfkey(u32 u) {
    return __uint_as_float((u & 0x80000000u) ? (u & 0x7FFFFFFFu) : ~u);
}

// ---------------------------------------------------------------------------
// Kernel 1: per-row squared norms + p = x@(W1a-W1b)+b1, q = x@W1b
// ---------------------------------------------------------------------------
__global__ __launch_bounds__(256) void pq_kernel(const float* __restrict__ x,
                                                 const float* __restrict__ W1,
                                                 const float* __restrict__ b1) {
    __shared__ float sx[8 * D];
    const int i0 = blockIdx.x * 8;
    const int t = threadIdx.x;

    for (int u = t; u < 8 * D; u += 256) sx[u] = x[i0 * D + u];
    __syncthreads();

    if (t < 8) {
        float s = 0.f;
        #pragma unroll
        for (int d = 0; d < D; d++) { float v = sx[t * D + d]; s = fmaf(v, v, s); }
        g_sq[i0 + t] = s;
    }

    float acc[8];
    #pragma unroll
    for (int m = 0; m < 8; m++) acc[m] = 0.f;

    if (t < DO) {
        const int c = t;
        for (int d = 0; d < D; d++) {
            float w = W1[d * DO + c] - W1[(D + d) * DO + c];
            #pragma unroll
            for (int m = 0; m < 8; m++) acc[m] = fmaf(sx[m * D + d], w, acc[m]);
        }
        float bb = b1[c];
        #pragma unroll
        for (int m = 0; m < 8; m++) g_p[(size_t)(i0 + m) * DO + c] = acc[m] + bb;
    } else {
        const int c = t - DO;
        for (int d = 0; d < D; d++) {
            float w = W1[(D + d) * DO + c];
            #pragma unroll
            for (int m = 0; m < 8; m++) acc[m] = fmaf(sx[m * D + d], w, acc[m]);
        }
        #pragma unroll
        for (int m = 0; m < 8; m++) g_q[(size_t)(i0 + m) * DO + c] = acc[m];
    }
}

// ---------------------------------------------------------------------------
// Kernel 2a: phase A — exact top-16 per (row, 128-j subsegment), j < 1024.
// grid = (64, 8). R11-validated.
// ---------------------------------------------------------------------------
__global__ __launch_bounds__(128, 4) void knnA_kernel(const float* __restrict__ x) {
    __shared__ ulonglong2 sj[TJ * 16];
    __shared__ float ssq[TJ];
    const int tid = threadIdx.x;
    const int i = blockIdx.x * 128 + tid;
    const int s = blockIdx.y;

    ulonglong2 xi[16];
    const ulonglong2* xr = reinterpret_cast<const ulonglong2*>(x) + (size_t)i * 16;
    #pragma unroll
    for (int c = 0; c < 16; c++) xi[c] = xr[c];
    const float sqi = g_sq[i];

    float kd[K];
    int   kj[K];
    #pragma unroll
    for (int n = 0; n < K; n++) { kd[n] = 3.4e38f; kj[n] = 0; }

    const int jbeg = s * JSEGA, jend = jbeg + JSEGA;
    for (int jb = jbeg; jb < jend; jb += TJ) {
        const ulonglong2* gs = reinterpret_cast<const ulonglong2*>(x) + (size_t)jb * 16;
        #pragma unroll
        for (int u = tid; u < TJ * 16; u += 128) sj[u] = gs[u];
        if (tid < TJ) ssq[tid] = g_sq[jb + tid];
        __syncthreads();

        #pragma unroll 2
        for (int jj = 0; jj < TJ; jj++) {
            u64 a0 = 0ull, a1 = 0ull, a2 = 0ull, a3 = 0ull;
            #pragma unroll
            for (int c = 0; c < 16; c += 2) {
                ulonglong2 v0 = sj[jj * 16 + c];
                ulonglong2 v1 = sj[jj * 16 + c + 1];
                a0 = ffma2(xi[c].x, v0.x, a0);
                a1 = ffma2(xi[c].y, v0.y, a1);
                a2 = ffma2(xi[c + 1].x, v1.x, a2);
                a3 = ffma2(xi[c + 1].y, v1.y, a3);
            }
            u64 st = fadd2(fadd2(a0, a1), fadd2(a2, a3));
            unsigned lo, hi;
            asm("mov.b64 {%0, %1}, %2;" : "=r"(lo), "=r"(hi) : "l"(st));
            float dot = __uint_as_float(lo) + __uint_as_float(hi);
            float dist = fmaf(-2.f, dot, sqi + ssq[jj]);
            if (dist < kd[K - 1]) {
                kd[K - 1] = dist; kj[K - 1] = jb + jj;
                #pragma unroll
                for (int n = K - 1; n > 0; n--) {
                    if (kd[n] < kd[n - 1]) {
                        float td = kd[n]; kd[n] = kd[n - 1]; kd[n - 1] = td;
                        int   tj = kj[n]; kj[n] = kj[n - 1]; kj[n - 1] = tj;
                    } else break;
                }
            }
        }
        __syncthreads();
    }

    u64* dst = g_ck + ((size_t)i * SEGA + s) * K;
    #pragma unroll
    for (int n = 0; n < K; n++)
        dst[n] = ((u64)fkey(kd[n]) << 32) | (unsigned)kj[n];
}

// ---------------------------------------------------------------------------
// Kernel 2b: threshold — exact 16th-smallest key of each row's 128 A-keys.
// R11-validated (thread per row).
// ---------------------------------------------------------------------------
__global__ __launch_bounds__(128) void thresh_kernel() {
    const int i = blockIdx.x * 128 + threadIdx.x;
    const u64* src = g_ck + (size_t)i * SEGA * K;

    u64 kd[K];
    #pragma unroll
    for (int n = 0; n < K; n++) kd[n] = 0xFFFFFFFFFFFFFFFFull;

    for (int u = 0; u < SEGA * K; u++) {
        u64 e = src[u];
        if (e < kd[K - 1]) {
            kd[K - 1] = e;
            #pragma unroll
            for (int n = K - 1; n > 0; n--) {
                if (kd[n] < kd[n - 1]) { u64 tm = kd[n]; kd[n] = kd[n - 1]; kd[n - 1] = tm; }
                else break;
            }
        }
    }
    g_thr[i] = unfkey((u32)(kd[K - 1] >> 32));
}

// ---------------------------------------------------------------------------
// Kernel 2c: phase B v2 — fixed-threshold scan, j in [1024, 8192),
// 2 rows/thread, LEAN hot loop: unroll 1, inline rare predicated append
// (no sd buffer / mask / drain). Target 3 CTAs/SM without spills.
// grid = (32, 14), block 128.
// ---------------------------------------------------------------------------
__global__ __launch_bounds__(128, 3) void knnB_kernel(const float* __restrict__ x) {
    __shared__ ulonglong2 sj[TJ * 16];
    __shared__ float ssq[TJ];
    const int tid = threadIdx.x;
    const int iA = blockIdx.x * 256 + tid;
    const int iB = iA + 128;
    const int s = blockIdx.y;

    ulonglong2 xa[16], xb[16];
    const ulonglong2* ra = reinterpret_cast<const ulonglong2*>(x) + (size_t)iA * 16;
    const ulonglong2* rb = reinterpret_cast<const ulonglong2*>(x) + (size_t)iB * 16;
    #pragma unroll
    for (int c = 0; c < 16; c++) { xa[c] = ra[c]; xb[c] = rb[c]; }
    const float sqa = g_sq[iA], sqb = g_sq[iB];
    const float tha = g_thr[iA], thb = g_thr[iB];

    u64* cpa = g_cand + ((size_t)iA * SEGB + s) * CAP;
    u64* cpb = g_cand + ((size_t)iB * SEGB + s) * CAP;
    int ca = 0, cb = 0;

    const int jbeg = JB0 + s * JSEGB, jend = jbeg + JSEGB;
    for (int jb = jbeg; jb < jend; jb += TJ) {
        const ulonglong2* gs = reinterpret_cast<const ulonglong2*>(x) + (size_t)jb * 16;
        #pragma unroll
        for (int u = tid; u < TJ * 16; u += 128) sj[u] = gs[u];
        if (tid < TJ) ssq[tid] = g_sq[jb + tid];
        __syncthreads();

        #pragma unroll 1
        for (int jj = 0; jj < TJ; jj++) {
            u64 a0 = 0ull, a1 = 0ull, a2 = 0ull, a3 = 0ull;
            u64 b0 = 0ull, b1 = 0ull, b2 = 0ull, b3 = 0ull;
            #pragma unroll
            for (int c = 0; c < 16; c += 2) {
                ulonglong2 v0 = sj[jj * 16 + c];
                ulonglong2 v1 = sj[jj * 16 + c + 1];
                a0 = ffma2(xa[c].x, v0.x, a0);
                a1 = ffma2(xa[c].y, v0.y, a1);
                a2 = ffma2(xa[c + 1].x, v1.x, a2);
                a3 = ffma2(xa[c + 1].y, v1.y, a3);
                b0 = ffma2(xb[c].x, v0.x, b0);
                b1 = ffma2(xb[c].y, v0.y, b1);
                b2 = ffma2(xb[c + 1].x, v1.x, b2);
                b3 = ffma2(xb[c + 1].y, v1.y, b3);
            }
            const float sjv = ssq[jj];
            u64 sta = fadd2(fadd2(a0, a1), fadd2(a2, a3));
            u64 stb = fadd2(fadd2(b0, b1), fadd2(b2, b3));
            unsigned lo, hi;
            asm("mov.b64 {%0, %1}, %2;" : "=r"(lo), "=r"(hi) : "l"(sta));
            float dA = fmaf(-2.f, __uint_as_float(lo) + __uint_as_float(hi),
                            sqa + sjv);
            asm("mov.b64 {%0, %1}, %2;" : "=r"(lo), "=r"(hi) : "l"(stb));
            float dB = fmaf(-2.f, __uint_as_float(lo) + __uint_as_float(hi),
                            sqb + sjv);
            if (dA <= tha) {
                cpa[(ca < CAP) ? ca : (CAP - 1)] =
                    ((u64)fkey(dA) << 32) | (u32)(jb + jj);
                ca++;
            }
            if (dB <= thb) {
                cpb[(cb < CAP) ? cb : (CAP - 1)] =
                    ((u64)fkey(dB) << 32) | (u32)(jb + jj);
                cb++;
            }
        }
        __syncthreads();
    }

    g_cnt[iA * SEGB + s] = (ca < CAP) ? ca : CAP;
    g_cnt[iB * SEGB + s] = (cb < CAP) ? cb : CAP;
}

// ---------------------------------------------------------------------------
// Kernel 3: merge — warp per row over 128 A-keys + appended B-keys;
// per-lane sorted top-16, then 16-round warp-min extraction. R11-validated.
// ---------------------------------------------------------------------------
__global__ __launch_bounds__(256) void merge_kernel() {
    const int t = threadIdx.x;
    const int w = t >> 5, lane = t & 31;
    const int i = blockIdx.x * 8 + w;

    u64 kd[K];
    #pragma unroll
    for (int n = 0; n < K; n++) kd[n] = 0xFFFFFFFFFFFFFFFFull;

    const u64* ak = g_ck + (size_t)i * SEGA * K;
    for (int u = lane; u < SEGA * K; u += 32) {
        u64 e = ak[u];
        if (e < kd[K - 1]) {
            kd[K - 1] = e;
            #pragma unroll
            for (int n = K - 1; n > 0; n--) {
                if (kd[n] < kd[n - 1]) { u64 tm = kd[n]; kd[n] = kd[n - 1]; kd[n - 1] = tm; }
                else break;
            }
        }
    }
    for (int s = 0; s < SEGB; s++) {
        const int c = g_cnt[i * SEGB + s];
        const u64* p = g_cand + ((size_t)i * SEGB + s) * CAP;
        for (int u = lane; u < c; u += 32) {
            u64 e = p[u];
            if (e < kd[K - 1]) {
                kd[K - 1] = e;
                #pragma unroll
                for (int n = K - 1; n > 0; n--) {
                    if (kd[n] < kd[n - 1]) { u64 tm = kd[n]; kd[n] = kd[n - 1]; kd[n - 1] = tm; }
                    else break;
                }
            }
        }
    }

    for (int r = 0; r < K; r++) {
        u64 h = kd[0];
        u64 m = h;
        #pragma unroll
        for (int off = 16; off > 0; off >>= 1) {
            u64 o = __shfl_down_sync(0xFFFFFFFFu, m, off);
            if (o < m) m = o;
        }
        m = __shfl_sync(0xFFFFFFFFu, m, 0);
        if (h == m) {
            g_nbr[(size_t)i * K + r] = (int)(m & 0xFFFFFFFFull);
            #pragma unroll
            for (int c = 0; c < K - 1; c++) kd[c] = kd[c + 1];
            kd[K - 1] = 0xFFFFFFFFFFFFFFFFull;
        }
    }
}

// ---------------------------------------------------------------------------
// Kernel 4: aggregate r = mean_n relu(p_i + q_jn), out = r@W2 + b2.
// R11-validated (block 128 = one row).
// ---------------------------------------------------------------------------
__global__ __launch_bounds__(128) void agg_kernel(const float* __restrict__ W2,
                                                  const float* __restrict__ b2,
                                                  float* __restrict__ out) {
    __shared__ int snbr[K];
    __shared__ float sr[DO];
    const int i = blockIdx.x;
    const int t = threadIdx.x;

    if (t < K) snbr[t] = g_nbr[(size_t)i * K + t];
    __syncthreads();

    float p = g_p[(size_t)i * DO + t];
    float acc = 0.f;
    #pragma unroll
    for (int n = 0; n < K; n++) {
        int j = snbr[n];
        acc += fmaxf(p + g_q[(size_t)j * DO + t], 0.f);
    }
    sr[t] = acc * (1.f / K);
    __syncthreads();

    float o = b2[t];
    #pragma unroll 8
    for (int d = 0; d < DO; d++)
        o = fmaf(sr[d], W2[d * DO + t], o);
    out[(size_t)i * DO + t] = o;
}

// ---------------------------------------------------------------------------
extern "C" void kernel_launch(void* const* d_in, const int* in_sizes, int n_in,
                              void* d_out, int out_size) {
    const float* x  = (const float*)d_in[0];
    const float* W1 = (const float*)d_in[1];
    const float* b1 = (const float*)d_in[2];
    const float* W2 = (const float*)d_in[3];
    const float* b2 = (const float*)d_in[4];
    float* out = (float*)d_out;

    pq_kernel<<<NN / 8, 256>>>(x, W1, b1);
    knnA_kernel<<<dim3(NN / 128, SEGA), 128>>>(x);
    thresh_kernel<<<NN / 128, 128>>>();
    knnB_kernel<<<dim3(NN / 256, SEGB), 128>>>(x);
    merge_kernel<<<NN / 8, 256>>>();
    agg_kernel<<<NN, 128>>>(W2, b2, out);
}

// round 15
// speedup vs baseline: 1.0145x; 1.0145x over previous
#include <cuda_runtime.h>
#include <cstdint>

#define NN 8192
#define D 64
#define DO 128
#define K 16

#define SEGA 2
#define JSEGA 128
#define SEGB 16
#define JSEGB 512
#define JB0 0
#define CAP 96
#define TJ 64

typedef unsigned long long u64;
typedef unsigned int u32;

// Scratch (module-scope device arrays; no runtime allocs)
__device__ float g_sq[NN];
__device__ float g_p[NN * DO];
__device__ float g_q[NN * DO];
__device__ u64 g_ck[NN * SEGA * K];
__device__ float g_thr[NN];
__device__ u64 g_cand[(size_t)NN * SEGB * CAP];
__device__ int g_cnt[NN * SEGB];
__device__ int g_nbr[NN * K];

// Packed fp32x2 math (FFMA2 path, PTX-only)
__device__ __forceinline__ u64 ffma2(u64 a, u64 b, u64 c) {
    u64 d;
    asm("fma.rn.f32x2 %0, %1, %2, %3;" : "=l"(d) : "l"(a), "l"(b), "l"(c));
    return d;
}
__device__ __forceinline__ u64 fadd2(u64 a, u64 b) {
    u64 d;
    asm("add.rn.f32x2 %0, %1, %2;" : "=l"(d) : "l"(a), "l"(b));
    return d;
}
__device__ __forceinline__ u32 fkey(float f) {
    u32 u = __float_as_uint(f);
    return (u & 0x80000000u) ? ~u : (u | 0x80000000u);
}
__device__ __forceinline__ float unfkey(u32 u) {
    return __uint_as_float((u & 0x80000000u) ? (u & 0x7FFFFFFFu) : ~u);
}

// ---------------------------------------------------------------------------
// Kernel 1: per-row squared norms + p = x@(W1a-W1b)+b1, q = x@W1b
// ---------------------------------------------------------------------------
__global__ __launch_bounds__(256) void pq_kernel(const float* __restrict__ x,
                                                 const float* __restrict__ W1,
                                                 const float* __restrict__ b1) {
    __shared__ float sx[8 * D];
    const int i0 = blockIdx.x * 8;
    const int t = threadIdx.x;

    for (int u = t; u < 8 * D; u += 256) sx[u] = x[i0 * D + u];
    __syncthreads();

    if (t < 8) {
        float s = 0.f;
        #pragma unroll
        for (int d = 0; d < D; d++) { float v = sx[t * D + d]; s = fmaf(v, v, s); }
        g_sq[i0 + t] = s;
    }

    float acc[8];
    #pragma unroll
    for (int m = 0; m < 8; m++) acc[m] = 0.f;

    if (t < DO) {
        const int c = t;
        for (int d = 0; d < D; d++) {
            float w = W1[d * DO + c] - W1[(D + d) * DO + c];
            #pragma unroll
            for (int m = 0; m < 8; m++) acc[m] = fmaf(sx[m * D + d], w, acc[m]);
        }
        float bb = b1[c];
        #pragma unroll
        for (int m = 0; m < 8; m++) g_p[(size_t)(i0 + m) * DO + c] = acc[m] + bb;
    } else {
        const int c = t - DO;
        for (int d = 0; d < D; d++) {
            float w = W1[(D + d) * DO + c];
            #pragma unroll
            for (int m = 0; m < 8; m++) acc[m] = fmaf(sx[m * D + d], w, acc[m]);
        }
        #pragma unroll
        for (int m = 0; m < 8; m++) g_q[(size_t)(i0 + m) * DO + c] = acc[m];
    }
}

// ---------------------------------------------------------------------------
// Kernel 2a: phase A — threshold sampler. Exact top-16 per (row, 128-j
// subsegment), j < 256. grid = (64, 2). R11-validated code, smaller range.
// ---------------------------------------------------------------------------
__global__ __launch_bounds__(128, 4) void knnA_kernel(const float* __restrict__ x) {
    __shared__ ulonglong2 sj[TJ * 16];
    __shared__ float ssq[TJ];
    const int tid = threadIdx.x;
    const int i = blockIdx.x * 128 + tid;
    const int s = blockIdx.y;

    ulonglong2 xi[16];
    const ulonglong2* xr = reinterpret_cast<const ulonglong2*>(x) + (size_t)i * 16;
    #pragma unroll
    for (int c = 0; c < 16; c++) xi[c] = xr[c];
    const float sqi = g_sq[i];

    float kd[K];
    int   kj[K];
    #pragma unroll
    for (int n = 0; n < K; n++) { kd[n] = 3.4e38f; kj[n] = 0; }

    const int jbeg = s * JSEGA, jend = jbeg + JSEGA;
    for (int jb = jbeg; jb < jend; jb += TJ) {
        const ulonglong2* gs = reinterpret_cast<const ulonglong2*>(x) + (size_t)jb * 16;
        #pragma unroll
        for (int u = tid; u < TJ * 16; u += 128) sj[u] = gs[u];
        if (tid < TJ) ssq[tid] = g_sq[jb + tid];
        __syncthreads();

        #pragma unroll 2
        for (int jj = 0; jj < TJ; jj++) {
            u64 a0 = 0ull, a1 = 0ull, a2 = 0ull, a3 = 0ull;
            #pragma unroll
            for (int c = 0; c < 16; c += 2) {
                ulonglong2 v0 = sj[jj * 16 + c];
                ulonglong2 v1 = sj[jj * 16 + c + 1];
                a0 = ffma2(xi[c].x, v0.x, a0);
                a1 = ffma2(xi[c].y, v0.y, a1);
                a2 = ffma2(xi[c + 1].x, v1.x, a2);
                a3 = ffma2(xi[c + 1].y, v1.y, a3);
            }
            u64 st = fadd2(fadd2(a0, a1), fadd2(a2, a3));
            unsigned lo, hi;
            asm("mov.b64 {%0, %1}, %2;" : "=r"(lo), "=r"(hi) : "l"(st));
            float dot = __uint_as_float(lo) + __uint_as_float(hi);
            float dist = fmaf(-2.f, dot, sqi + ssq[jj]);
            if (dist < kd[K - 1]) {
                kd[K - 1] = dist; kj[K - 1] = jb + jj;
                #pragma unroll
                for (int n = K - 1; n > 0; n--) {
                    if (kd[n] < kd[n - 1]) {
                        float td = kd[n]; kd[n] = kd[n - 1]; kd[n - 1] = td;
                        int   tj = kj[n]; kj[n] = kj[n - 1]; kj[n - 1] = tj;
                    } else break;
                }
            }
        }
        __syncthreads();
    }

    u64* dst = g_ck + ((size_t)i * SEGA + s) * K;
    #pragma unroll
    for (int n = 0; n < K; n++)
        dst[n] = ((u64)fkey(kd[n]) << 32) | (unsigned)kj[n];
}

// ---------------------------------------------------------------------------
// Kernel 2b: threshold — exact 16th-smallest key of each row's 32 A-keys.
// Thread per row (R11-validated pattern).
// ---------------------------------------------------------------------------
__global__ __launch_bounds__(128) void thresh_kernel() {
    const int i = blockIdx.x * 128 + threadIdx.x;
    const u64* src = g_ck + (size_t)i * SEGA * K;

    u64 kd[K];
    #pragma unroll
    for (int n = 0; n < K; n++) kd[n] = 0xFFFFFFFFFFFFFFFFull;

    for (int u = 0; u < SEGA * K; u++) {
        u64 e = src[u];
        if (e < kd[K - 1]) {
            kd[K - 1] = e;
            #pragma unroll
            for (int n = K - 1; n > 0; n--) {
                if (kd[n] < kd[n - 1]) { u64 tm = kd[n]; kd[n] = kd[n - 1]; kd[n - 1] = tm; }
                else break;
            }
        }
    }
    g_thr[i] = unfkey((u32)(kd[K - 1] >> 32));
}

// ---------------------------------------------------------------------------
// Kernel 2c: phase B — fixed-threshold scan over the FULL j range [0, 8192),
// 2 rows/thread. grid = (32, 16), block 128. EXACT R11/R13 hot code
// (unroll 2, mask + sd-buffer drain, natural 208 regs, occ 2 — validated).
// ---------------------------------------------------------------------------
__global__ __launch_bounds__(128, 2) void knnB_kernel(const float* __restrict__ x) {
    __shared__ ulonglong2 sj[TJ * 16];
    __shared__ float ssq[TJ];
    __shared__ float sd[16 * 132];    // rows 0-7: row A dists, 8-15: row B
    const int tid = threadIdx.x;
    const int iA = blockIdx.x * 256 + tid;
    const int iB = iA + 128;
    const int s = blockIdx.y;

    ulonglong2 xa[16], xb[16];
    const ulonglong2* ra = reinterpret_cast<const ulonglong2*>(x) + (size_t)iA * 16;
    const ulonglong2* rb = reinterpret_cast<const ulonglong2*>(x) + (size_t)iB * 16;
    #pragma unroll
    for (int c = 0; c < 16; c++) { xa[c] = ra[c]; xb[c] = rb[c]; }
    const float sqa = g_sq[iA], sqb = g_sq[iB];
    const float tha = g_thr[iA], thb = g_thr[iB];

    u64* cpa = g_cand + ((size_t)iA * SEGB + s) * CAP;
    u64* cpb = g_cand + ((size_t)iB * SEGB + s) * CAP;
    int ca = 0, cb = 0;

    const int jbeg = JB0 + s * JSEGB, jend = jbeg + JSEGB;
    for (int jb = jbeg; jb < jend; jb += TJ) {
        const ulonglong2* gs = reinterpret_cast<const ulonglong2*>(x) + (size_t)jb * 16;
        #pragma unroll
        for (int u = tid; u < TJ * 16; u += 128) sj[u] = gs[u];
        if (tid < TJ) ssq[tid] = g_sq[jb + tid];
        __syncthreads();

        #pragma unroll 1
        for (int c8 = 0; c8 < TJ / 8; c8++) {
            u32 ma = 0, mb = 0;
            #pragma unroll 2
            for (int u = 0; u < 8; u++) {
                const int jj = c8 * 8 + u;
                u64 a0 = 0ull, a1 = 0ull, a2 = 0ull, a3 = 0ull;
                u64 b0 = 0ull, b1 = 0ull, b2 = 0ull, b3 = 0ull;
                #pragma unroll
                for (int c = 0; c < 16; c += 2) {
                    ulonglong2 v0 = sj[jj * 16 + c];
                    ulonglong2 v1 = sj[jj * 16 + c + 1];
                    a0 = ffma2(xa[c].x, v0.x, a0);
                    a1 = ffma2(xa[c].y, v0.y, a1);
                    a2 = ffma2(xa[c + 1].x, v1.x, a2);
                    a3 = ffma2(xa[c + 1].y, v1.y, a3);
                    b0 = ffma2(xb[c].x, v0.x, b0);
                    b1 = ffma2(xb[c].y, v0.y, b1);
                    b2 = ffma2(xb[c + 1].x, v1.x, b2);
                    b3 = ffma2(xb[c + 1].y, v1.y, b3);
                }
                const float sjv = ssq[jj];
                u64 sta = fadd2(fadd2(a0, a1), fadd2(a2, a3));
                u64 stb = fadd2(fadd2(b0, b1), fadd2(b2, b3));
                unsigned lo, hi;
                asm("mov.b64 {%0, %1}, %2;" : "=r"(lo), "=r"(hi) : "l"(sta));
                float dA = fmaf(-2.f, __uint_as_float(lo) + __uint_as_float(hi),
                                sqa + sjv);
                asm("mov.b64 {%0, %1}, %2;" : "=r"(lo), "=r"(hi) : "l"(stb));
                float dB = fmaf(-2.f, __uint_as_float(lo) + __uint_as_float(hi),
                                sqb + sjv);
                sd[u * 132 + tid] = dA;
                sd[(8 + u) * 132 + tid] = dB;
                ma |= (dA <= tha) ? (1u << u) : 0u;
                mb |= (dB <= thb) ? (1u << u) : 0u;
            }
            // Drain (rare).
            while (ma) {
                int b = __ffs(ma) - 1;
                ma &= ma - 1;
                float dv = sd[b * 132 + tid];
                int jv = jb + c8 * 8 + b;
                int slot = (ca < CAP) ? ca : (CAP - 1);
                cpa[slot] = ((u64)fkey(dv) << 32) | (u32)jv;
                ca++;
            }
            while (mb) {
                int b = __ffs(mb) - 1;
                mb &= mb - 1;
                float dv = sd[(8 + b) * 132 + tid];
                int jv = jb + c8 * 8 + b;
                int slot = (cb < CAP) ? cb : (CAP - 1);
                cpb[slot] = ((u64)fkey(dv) << 32) | (u32)jv;
                cb++;
            }
        }
        __syncthreads();
    }

    g_cnt[iA * SEGB + s] = (ca < CAP) ? ca : CAP;
    g_cnt[iB * SEGB + s] = (cb < CAP) ? cb : CAP;
}

// ---------------------------------------------------------------------------
// Kernel 3: merge — warp per row over B candidates only (covers all j);
// per-lane sorted top-16, then 16-round warp-min extraction. R11-validated.
// ---------------------------------------------------------------------------
__global__ __launch_bounds__(256) void merge_kernel() {
    const int t = threadIdx.x;
    const int w = t >> 5, lane = t & 31;
    const int i = blockIdx.x * 8 + w;

    u64 kd[K];
    #pragma unroll
    for (int n = 0; n < K; n++) kd[n] = 0xFFFFFFFFFFFFFFFFull;

    for (int s = 0; s < SEGB; s++) {
        const int c = g_cnt[i * SEGB + s];
        const u64* p = g_cand + ((size_t)i * SEGB + s) * CAP;
        for (int u = lane; u < c; u += 32) {
            u64 e = p[u];
            if (e < kd[K - 1]) {
                kd[K - 1] = e;
                #pragma unroll
                for (int n = K - 1; n > 0; n--) {
                    if (kd[n] < kd[n - 1]) { u64 tm = kd[n]; kd[n] = kd[n - 1]; kd[n - 1] = tm; }
                    else break;
                }
            }
        }
    }

    for (int r = 0; r < K; r++) {
        u64 h = kd[0];
        u64 m = h;
        #pragma unroll
        for (int off = 16; off > 0; off >>= 1) {
            u64 o = __shfl_down_sync(0xFFFFFFFFu, m, off);
            if (o < m) m = o;
        }
        m = __shfl_sync(0xFFFFFFFFu, m, 0);
        if (h == m) {
            g_nbr[(size_t)i * K + r] = (int)(m & 0xFFFFFFFFull);
            #pragma unroll
            for (int c = 0; c < K - 1; c++) kd[c] = kd[c + 1];
            kd[K - 1] = 0xFFFFFFFFFFFFFFFFull;
        }
    }
}

// ---------------------------------------------------------------------------
// Kernel 4: aggregate r = mean_n relu(p_i + q_jn), out = r@W2 + b2.
// R11-validated (block 128 = one row).
// ---------------------------------------------------------------------------
__global__ __launch_bounds__(128) void agg_kernel(const float* __restrict__ W2,
                                                  const float* __restrict__ b2,
                                                  float* __restrict__ out) {
    __shared__ int snbr[K];
    __shared__ float sr[DO];
    const int i = blockIdx.x;
    const int t = threadIdx.x;

    if (t < K) snbr[t] = g_nbr[(size_t)i * K + t];
    __syncthreads();

    float p = g_p[(size_t)i * DO + t];
    float acc = 0.f;
    #pragma unroll
    for (int n = 0; n < K; n++) {
        int j = snbr[n];
        acc += fmaxf(p + g_q[(size_t)j * DO + t], 0.f);
    }
    sr[t] = acc * (1.f / K);
    __syncthreads();

    float o = b2[t];
    #pragma unroll 8
    for (int d = 0; d < DO; d++)
        o = fmaf(sr[d], W2[d * DO + t], o);
    out[(size_t)i * DO + t] = o;
}

// ---------------------------------------------------------------------------
extern "C" void kernel_launch(void* const* d_in, const int* in_sizes, int n_in,
                              void* d_out, int out_size) {
    const float* x  = (const float*)d_in[0];
    const float* W1 = (const float*)d_in[1];
    const float* b1 = (const float*)d_in[2];
    const float* W2 = (const float*)d_in[3];
    const float* b2 = (const float*)d_in[4];
    float* out = (float*)d_out;

    pq_kernel<<<NN / 8, 256>>>(x, W1, b1);
    knnA_kernel<<<dim3(NN / 128, SEGA), 128>>>(x);
    thresh_kernel<<<NN / 128, 128>>>();
    knnB_kernel<<<dim3(NN / 256, SEGB), 128>>>(x);
    merge_kernel<<<NN / 8, 256>>>();
    agg_kernel<<<NN, 128>>>(W2, b2, out);
}

// round 16
// speedup vs baseline: 1.0955x; 1.0799x over previous
#include <cuda_runtime.h>
#include <cstdint>

#define NN 8192
#define D 64
#define DO 128
#define K 16

#define SEGA 2          // A0: two 64-j subsegments covering j < 128
#define JSEGA 64
#define SEGA1 7         // A1: seven 128-j segments covering [128, 1024)
#define JSEGA1 128
#define JA1_0 128
#define CAP1 48
#define SEGB 14         // B: fourteen 512-j segments covering [1024, 8192)
#define JSEGB 512
#define JB0 1024
#define CAP 96
#define TJ 64

typedef unsigned long long u64;
typedef unsigned int u32;

// Scratch (module-scope device arrays; no runtime allocs)
__device__ float g_sq[NN];
__device__ float g_p[NN * DO];
__device__ float g_q[NN * DO];
__device__ u64 g_ck[NN * SEGA * K];
__device__ float g_thr0[NN];
__device__ float g_thr[NN];
__device__ u64 g_cand1[(size_t)NN * SEGA1 * CAP1];
__device__ int g_cnt1[NN * SEGA1];
__device__ u64 g_cand[(size_t)NN * SEGB * CAP];
__device__ int g_cnt[NN * SEGB];
__device__ int g_nbr[NN * K];

// Packed fp32x2 math (FFMA2 path, PTX-only)
__device__ __forceinline__ u64 ffma2(u64 a, u64 b, u64 c) {
    u64 d;
    asm("fma.rn.f32x2 %0, %1, %2, %3;" : "=l"(d) : "l"(a), "l"(b), "l"(c));
    return d;
}
__device__ __forceinline__ u64 fadd2(u64 a, u64 b) {
    u64 d;
    asm("add.rn.f32x2 %0, %1, %2;" : "=l"(d) : "l"(a), "l"(b));
    return d;
}
__device__ __forceinline__ u32 fkey(float f) {
    u32 u = __float_as_uint(f);
    return (u & 0x80000000u) ? ~u : (u | 0x80000000u);
}
__device__ __forceinline__ float unfkey(u32 u) {
    return __uint_as_float((u & 0x80000000u) ? (u & 0x7FFFFFFFu) : ~u);
}

// ---------------------------------------------------------------------------
// Kernel 1: per-row squared norms + p = x@(W1a-W1b)+b1, q = x@W1b
// ---------------------------------------------------------------------------
__global__ __launch_bounds__(256) void pq_kernel(const float* __restrict__ x,
                                                 const float* __restrict__ W1,
                                                 const float* __restrict__ b1) {
    __shared__ float sx[8 * D];
    const int i0 = blockIdx.x * 8;
    const int t = threadIdx.x;

    for (int u = t; u < 8 * D; u += 256) sx[u] = x[i0 * D + u];
    __syncthreads();

    if (t < 8) {
        float s = 0.f;
        #pragma unroll
        for (int d = 0; d < D; d++) { float v = sx[t * D + d]; s = fmaf(v, v, s); }
        g_sq[i0 + t] = s;
    }

    float acc[8];
    #pragma unroll
    for (int m = 0; m < 8; m++) acc[m] = 0.f;

    if (t < DO) {
        const int c = t;
        for (int d = 0; d < D; d++) {
            float w = W1[d * DO + c] - W1[(D + d) * DO + c];
            #pragma unroll
            for (int m = 0; m < 8; m++) acc[m] = fmaf(sx[m * D + d], w, acc[m]);
        }
        float bb = b1[c];
        #pragma unroll
        for (int m = 0; m < 8; m++) g_p[(size_t)(i0 + m) * DO + c] = acc[m] + bb;
    } else {
        const int c = t - DO;
        for (int d = 0; d < D; d++) {
            float w = W1[(D + d) * DO + c];
            #pragma unroll
            for (int m = 0; m < 8; m++) acc[m] = fmaf(sx[m * D + d], w, acc[m]);
        }
        #pragma unroll
        for (int m = 0; m < 8; m++) g_q[(size_t)(i0 + m) * DO + c] = acc[m];
    }
}

// ---------------------------------------------------------------------------
// Kernel 2a: A0 — exact top-16 per (row, 64-j subsegment), j < 128.
// grid = (64, 2). R11-validated hot code, tiny range.
// ---------------------------------------------------------------------------
__global__ __launch_bounds__(128, 4) void knnA0_kernel(const float* __restrict__ x) {
    __shared__ ulonglong2 sj[TJ * 16];
    __shared__ float ssq[TJ];
    const int tid = threadIdx.x;
    const int i = blockIdx.x * 128 + tid;
    const int s = blockIdx.y;

    ulonglong2 xi[16];
    const ulonglong2* xr = reinterpret_cast<const ulonglong2*>(x) + (size_t)i * 16;
    #pragma unroll
    for (int c = 0; c < 16; c++) xi[c] = xr[c];
    const float sqi = g_sq[i];

    float kd[K];
    int   kj[K];
    #pragma unroll
    for (int n = 0; n < K; n++) { kd[n] = 3.4e38f; kj[n] = 0; }

    const int jb = s * JSEGA;   // one 64-j tile per block
    {
        const ulonglong2* gs = reinterpret_cast<const ulonglong2*>(x) + (size_t)jb * 16;
        #pragma unroll
        for (int u = tid; u < TJ * 16; u += 128) sj[u] = gs[u];
        if (tid < TJ) ssq[tid] = g_sq[jb + tid];
        __syncthreads();

        #pragma unroll 2
        for (int jj = 0; jj < TJ; jj++) {
            u64 a0 = 0ull, a1 = 0ull, a2 = 0ull, a3 = 0ull;
            #pragma unroll
            for (int c = 0; c < 16; c += 2) {
                ulonglong2 v0 = sj[jj * 16 + c];
                ulonglong2 v1 = sj[jj * 16 + c + 1];
                a0 = ffma2(xi[c].x, v0.x, a0);
                a1 = ffma2(xi[c].y, v0.y, a1);
                a2 = ffma2(xi[c + 1].x, v1.x, a2);
                a3 = ffma2(xi[c + 1].y, v1.y, a3);
            }
            u64 st = fadd2(fadd2(a0, a1), fadd2(a2, a3));
            unsigned lo, hi;
            asm("mov.b64 {%0, %1}, %2;" : "=r"(lo), "=r"(hi) : "l"(st));
            float dot = __uint_as_float(lo) + __uint_as_float(hi);
            float dist = fmaf(-2.f, dot, sqi + ssq[jj]);
            if (dist < kd[K - 1]) {
                kd[K - 1] = dist; kj[K - 1] = jb + jj;
                #pragma unroll
                for (int n = K - 1; n > 0; n--) {
                    if (kd[n] < kd[n - 1]) {
                        float td = kd[n]; kd[n] = kd[n - 1]; kd[n - 1] = td;
                        int   tj = kj[n]; kj[n] = kj[n - 1]; kj[n - 1] = tj;
                    } else break;
                }
            }
        }
    }

    u64* dst = g_ck + ((size_t)i * SEGA + s) * K;
    #pragma unroll
    for (int n = 0; n < K; n++)
        dst[n] = ((u64)fkey(kd[n]) << 32) | (unsigned)kj[n];
}

// ---------------------------------------------------------------------------
// Kernel 2b: thr0 — exact 16th-smallest of each row's 32 A0 keys.
// Thread per row.
// ---------------------------------------------------------------------------
__global__ __launch_bounds__(128) void thr0_kernel() {
    const int i = blockIdx.x * 128 + threadIdx.x;
    const u64* src = g_ck + (size_t)i * SEGA * K;

    u64 kd[K];
    #pragma unroll
    for (int n = 0; n < K; n++) kd[n] = 0xFFFFFFFFFFFFFFFFull;

    for (int u = 0; u < SEGA * K; u++) {
        u64 e = src[u];
        if (e < kd[K - 1]) {
            kd[K - 1] = e;
            #pragma unroll
            for (int n = K - 1; n > 0; n--) {
                if (kd[n] < kd[n - 1]) { u64 tm = kd[n]; kd[n] = kd[n - 1]; kd[n - 1] = tm; }
                else break;
            }
        }
    }
    g_thr0[i] = unfkey((u32)(kd[K - 1] >> 32));
}

// ---------------------------------------------------------------------------
// Shared threshold-scan body (validated R11/R13 knnB hot code), used by both
// A1 and B via template params.
// ---------------------------------------------------------------------------
template <int NSEG, int CAPX>
__device__ __forceinline__ void thr_scan(const float* __restrict__ x,
                                         const float* __restrict__ thr_arr,
                                         u64* __restrict__ cand,
                                         int* __restrict__ cnt,
                                         int jbeg, int jendx,
                                         ulonglong2* sj, float* ssq, float* sd) {
    const int tid = threadIdx.x;
    const int iA = blockIdx.x * 256 + tid;
    const int iB = iA + 128;
    const int s = blockIdx.y;

    ulonglong2 xa[16], xb[16];
    const ulonglong2* ra = reinterpret_cast<const ulonglong2*>(x) + (size_t)iA * 16;
    const ulonglong2* rb = reinterpret_cast<const ulonglong2*>(x) + (size_t)iB * 16;
    #pragma unroll
    for (int c = 0; c < 16; c++) { xa[c] = ra[c]; xb[c] = rb[c]; }
    const float sqa = g_sq[iA], sqb = g_sq[iB];
    const float tha = thr_arr[iA], thb = thr_arr[iB];

    u64* cpa = cand + ((size_t)iA * NSEG + s) * CAPX;
    u64* cpb = cand + ((size_t)iB * NSEG + s) * CAPX;
    int ca = 0, cb = 0;

    for (int jb = jbeg; jb < jendx; jb += TJ) {
        const ulonglong2* gs = reinterpret_cast<const ulonglong2*>(x) + (size_t)jb * 16;
        #pragma unroll
        for (int u = tid; u < TJ * 16; u += 128) sj[u] = gs[u];
        if (tid < TJ) ssq[tid] = g_sq[jb + tid];
        __syncthreads();

        #pragma unroll 1
        for (int c8 = 0; c8 < TJ / 8; c8++) {
            u32 ma = 0, mb = 0;
            #pragma unroll 2
            for (int u = 0; u < 8; u++) {
                const int jj = c8 * 8 + u;
                u64 a0 = 0ull, a1 = 0ull, a2 = 0ull, a3 = 0ull;
                u64 b0 = 0ull, b1 = 0ull, b2 = 0ull, b3 = 0ull;
                #pragma unroll
                for (int c = 0; c < 16; c += 2) {
                    ulonglong2 v0 = sj[jj * 16 + c];
                    ulonglong2 v1 = sj[jj * 16 + c + 1];
                    a0 = ffma2(xa[c].x, v0.x, a0);
                    a1 = ffma2(xa[c].y, v0.y, a1);
                    a2 = ffma2(xa[c + 1].x, v1.x, a2);
                    a3 = ffma2(xa[c + 1].y, v1.y, a3);
                    b0 = ffma2(xb[c].x, v0.x, b0);
                    b1 = ffma2(xb[c].y, v0.y, b1);
                    b2 = ffma2(xb[c + 1].x, v1.x, b2);
                    b3 = ffma2(xb[c + 1].y, v1.y, b3);
                }
                const float sjv = ssq[jj];
                u64 sta = fadd2(fadd2(a0, a1), fadd2(a2, a3));
                u64 stb = fadd2(fadd2(b0, b1), fadd2(b2, b3));
                unsigned lo, hi;
                asm("mov.b64 {%0, %1}, %2;" : "=r"(lo), "=r"(hi) : "l"(sta));
                float dA = fmaf(-2.f, __uint_as_float(lo) + __uint_as_float(hi),
                                sqa + sjv);
                asm("mov.b64 {%0, %1}, %2;" : "=r"(lo), "=r"(hi) : "l"(stb));
                float dB = fmaf(-2.f, __uint_as_float(lo) + __uint_as_float(hi),
                                sqb + sjv);
                sd[u * 132 + tid] = dA;
                sd[(8 + u) * 132 + tid] = dB;
                ma |= (dA <= tha) ? (1u << u) : 0u;
                mb |= (dB <= thb) ? (1u << u) : 0u;
            }
            while (ma) {
                int b = __ffs(ma) - 1;
                ma &= ma - 1;
                float dv = sd[b * 132 + tid];
                int jv = jb + c8 * 8 + b;
                cpa[(ca < CAPX) ? ca : (CAPX - 1)] = ((u64)fkey(dv) << 32) | (u32)jv;
                ca++;
            }
            while (mb) {
                int b = __ffs(mb) - 1;
                mb &= mb - 1;
                float dv = sd[(8 + b) * 132 + tid];
                int jv = jb + c8 * 8 + b;
                cpb[(cb < CAPX) ? cb : (CAPX - 1)] = ((u64)fkey(dv) << 32) | (u32)jv;
                cb++;
            }
        }
        __syncthreads();
    }

    cnt[iA * NSEG + s] = (ca < CAPX) ? ca : CAPX;
    cnt[iB * NSEG + s] = (cb < CAPX) ? cb : CAPX;
}

// Kernel 2c: A1 — threshold scan (thr0) over j in [128, 1024). grid (32, 7).
__global__ __launch_bounds__(128, 2) void knnA1_kernel(const float* __restrict__ x) {
    __shared__ ulonglong2 sj[TJ * 16];
    __shared__ float ssq[TJ];
    __shared__ float sd[16 * 132];
    const int jbeg = JA1_0 + blockIdx.y * JSEGA1;
    thr_scan<SEGA1, CAP1>(x, g_thr0, g_cand1, g_cnt1, jbeg, jbeg + JSEGA1,
                          sj, ssq, sd);
}

// Kernel 2e: B — threshold scan (thr2) over j in [1024, 8192). grid (32, 14).
__global__ __launch_bounds__(128, 2) void knnB_kernel(const float* __restrict__ x) {
    __shared__ ulonglong2 sj[TJ * 16];
    __shared__ float ssq[TJ];
    __shared__ float sd[16 * 132];
    const int jbeg = JB0 + blockIdx.y * JSEGB;
    thr_scan<SEGB, CAP>(x, g_thr, g_cand, g_cnt, jbeg, jbeg + JSEGB,
                        sj, ssq, sd);
}

// ---------------------------------------------------------------------------
// Kernel 2d: thresh2 — exact 16th of A0 keys + A1 candidates = exact 16th of
// j in [0, 1024). Warp per row (merge-validated pattern). grid NN/8, 256 thr.
// ---------------------------------------------------------------------------
__global__ __launch_bounds__(256) void thresh2_kernel() {
    const int t = threadIdx.x;
    const int w = t >> 5, lane = t & 31;
    const int i = blockIdx.x * 8 + w;

    u64 kd[K];
    #pragma unroll
    for (int n = 0; n < K; n++) kd[n] = 0xFFFFFFFFFFFFFFFFull;

    const u64* ak = g_ck + (size_t)i * SEGA * K;
    if (lane < SEGA * K) {
        u64 e = ak[lane];
        kd[K - 1] = e;   // first element, list empty: direct place then sort later
        // simple insert (list was all-max)
        #pragma unroll
        for (int n = K - 1; n > 0; n--) {
            if (kd[n] < kd[n - 1]) { u64 tm = kd[n]; kd[n] = kd[n - 1]; kd[n - 1] = tm; }
            else break;
        }
    }
    for (int s = 0; s < SEGA1; s++) {
        const int c = g_cnt1[i * SEGA1 + s];
        const u64* p = g_cand1 + ((size_t)i * SEGA1 + s) * CAP1;
        for (int u = lane; u < c; u += 32) {
            u64 e = p[u];
            if (e < kd[K - 1]) {
                kd[K - 1] = e;
                #pragma unroll
                for (int n = K - 1; n > 0; n--) {
                    if (kd[n] < kd[n - 1]) { u64 tm = kd[n]; kd[n] = kd[n - 1]; kd[n - 1] = tm; }
                    else break;
                }
            }
        }
    }

    u64 last = 0;
    for (int r = 0; r < K; r++) {
        u64 h = kd[0];
        u64 m = h;
        #pragma unroll
        for (int off = 16; off > 0; off >>= 1) {
            u64 o = __shfl_down_sync(0xFFFFFFFFu, m, off);
            if (o < m) m = o;
        }
        m = __shfl_sync(0xFFFFFFFFu, m, 0);
        if (h == m) {
            #pragma unroll
            for (int c = 0; c < K - 1; c++) kd[c] = kd[c + 1];
            kd[K - 1] = 0xFFFFFFFFFFFFFFFFull;
        }
        last = m;
    }
    if (lane == 0) g_thr[i] = unfkey((u32)(last >> 32));
}

// ---------------------------------------------------------------------------
// Kernel 3: merge — warp per row over A0 keys + A1 cands + B cands.
// ---------------------------------------------------------------------------
__global__ __launch_bounds__(256) void merge_kernel() {
    const int t = threadIdx.x;
    const int w = t >> 5, lane = t & 31;
    const int i = blockIdx.x * 8 + w;

    u64 kd[K];
    #pragma unroll
    for (int n = 0; n < K; n++) kd[n] = 0xFFFFFFFFFFFFFFFFull;

    const u64* ak = g_ck + (size_t)i * SEGA * K;
    if (lane < SEGA * K) {
        u64 e = ak[lane];
        kd[K - 1] = e;
        #pragma unroll
        for (int n = K - 1; n > 0; n--) {
            if (kd[n] < kd[n - 1]) { u64 tm = kd[n]; kd[n] = kd[n - 1]; kd[n - 1] = tm; }
            else break;
        }
    }
    for (int s = 0; s < SEGA1; s++) {
        const int c = g_cnt1[i * SEGA1 + s];
        const u64* p = g_cand1 + ((size_t)i * SEGA1 + s) * CAP1;
        for (int u = lane; u < c; u += 32) {
            u64 e = p[u];
            if (e < kd[K - 1]) {
                kd[K - 1] = e;
                #pragma unroll
                for (int n = K - 1; n > 0; n--) {
                    if (kd[n] < kd[n - 1]) { u64 tm = kd[n]; kd[n] = kd[n - 1]; kd[n - 1] = tm; }
                    else break;
                }
            }
        }
    }
    for (int s = 0; s < SEGB; s++) {
        const int c = g_cnt[i * SEGB + s];
        const u64* p = g_cand + ((size_t)i * SEGB + s) * CAP;
        for (int u = lane; u < c; u += 32) {
            u64 e = p[u];
            if (e < kd[K - 1]) {
                kd[K - 1] = e;
                #pragma unroll
                for (int n = K - 1; n > 0; n--) {
                    if (kd[n] < kd[n - 1]) { u64 tm = kd[n]; kd[n] = kd[n - 1]; kd[n - 1] = tm; }
                    else break;
                }
            }
        }
    }

    for (int r = 0; r < K; r++) {
        u64 h = kd[0];
        u64 m = h;
        #pragma unroll
        for (int off = 16; off > 0; off >>= 1) {
            u64 o = __shfl_down_sync(0xFFFFFFFFu, m, off);
            if (o < m) m = o;
        }
        m = __shfl_sync(0xFFFFFFFFu, m, 0);
        if (h == m) {
            g_nbr[(size_t)i * K + r] = (int)(m & 0xFFFFFFFFull);
            #pragma unroll
            for (int c = 0; c < K - 1; c++) kd[c] = kd[c + 1];
            kd[K - 1] = 0xFFFFFFFFFFFFFFFFull;
        }
    }
}

// ---------------------------------------------------------------------------
// Kernel 4: aggregate r = mean_n relu(p_i + q_jn), out = r@W2 + b2.
// R11-validated (block 128 = one row).
// ---------------------------------------------------------------------------
__global__ __launch_bounds__(128) void agg_kernel(const float* __restrict__ W2,
                                                  const float* __restrict__ b2,
                                                  float* __restrict__ out) {
    __shared__ int snbr[K];
    __shared__ float sr[DO];
    const int i = blockIdx.x;
    const int t = threadIdx.x;

    if (t < K) snbr[t] = g_nbr[(size_t)i * K + t];
    __syncthreads();

    float p = g_p[(size_t)i * DO + t];
    float acc = 0.f;
    #pragma unroll
    for (int n = 0; n < K; n++) {
        int j = snbr[n];
        acc += fmaxf(p + g_q[(size_t)j * DO + t], 0.f);
    }
    sr[t] = acc * (1.f / K);
    __syncthreads();

    float o = b2[t];
    #pragma unroll 8
    for (int d = 0; d < DO; d++)
        o = fmaf(sr[d], W2[d * DO + t], o);
    out[(size_t)i * DO + t] = o;
}

// ---------------------------------------------------------------------------
extern "C" void kernel_launch(void* const* d_in, const int* in_sizes, int n_in,
                              void* d_out, int out_size) {
    const float* x  = (const float*)d_in[0];
    const float* W1 = (const float*)d_in[1];
    const float* b1 = (const float*)d_in[2];
    const float* W2 = (const float*)d_in[3];
    const float* b2 = (const float*)d_in[4];
    float* out = (float*)d_out;

    pq_kernel<<<NN / 8, 256>>>(x, W1, b1);
    knnA0_kernel<<<dim3(NN / 128, SEGA), 128>>>(x);
    thr0_kernel<<<NN / 128, 128>>>();
    knnA1_kernel<<<dim3(NN / 256, SEGA1), 128>>>(x);
    thresh2_kernel<<<NN / 8, 256>>>();
    knnB_kernel<<<dim3(NN / 256, SEGB), 128>>>(x);
    merge_kernel<<<NN / 8, 256>>>();
    agg_kernel<<<NN, 128>>>(W2, b2, out);
}

// round 17
// speedup vs baseline: 1.2167x; 1.1106x over previous
#include <cuda_runtime.h>
#include <cstdint>

#define NN 8192
#define D 64
#define DO 128
#define K 16

#define SEGA 8
#define JSEGA 128
#define SEGB 14
#define JSEGB 512
#define JB0 1024
#define CAP 96
#define TJ 64
#define NTB (JSEGB / TJ)   // 8 tiles per B block

typedef unsigned long long u64;
typedef unsigned int u32;

// Scratch (module-scope device arrays; no runtime allocs)
__device__ float g_sq[NN];
__device__ float g_p[NN * DO];
__device__ float g_q[NN * DO];
__device__ u64 g_ck[NN * SEGA * K];
__device__ float g_thr[NN];
__device__ u64 g_cand[(size_t)NN * SEGB * CAP];
__device__ int g_cnt[NN * SEGB];
__device__ int g_nbr[NN * K];

// Packed fp32x2 math (FFMA2 path, PTX-only)
__device__ __forceinline__ u64 ffma2(u64 a, u64 b, u64 c) {
    u64 d;
    asm("fma.rn.f32x2 %0, %1, %2, %3;" : "=l"(d) : "l"(a), "l"(b), "l"(c));
    return d;
}
__device__ __forceinline__ u64 fadd2(u64 a, u64 b) {
    u64 d;
    asm("add.rn.f32x2 %0, %1, %2;" : "=l"(d) : "l"(a), "l"(b));
    return d;
}
__device__ __forceinline__ u32 fkey(float f) {
    u32 u = __float_as_uint(f);
    return (u & 0x80000000u) ? ~u : (u | 0x80000000u);
}
__device__ __forceinline__ float unfkey(u32 u) {
    return __uint_as_float((u & 0x80000000u) ? (u & 0x7FFFFFFFu) : ~u);
}

// cp.async helpers (LDGSTS — no data-register cost)
__device__ __forceinline__ void cp16(u32 dst, const void* src) {
    asm volatile("cp.async.cg.shared.global [%0], [%1], 16;"
                 :: "r"(dst), "l"(src) : "memory");
}
__device__ __forceinline__ void cp4(u32 dst, const void* src) {
    asm volatile("cp.async.ca.shared.global [%0], [%1], 4;"
                 :: "r"(dst), "l"(src) : "memory");
}
__device__ __forceinline__ void cp_commit() {
    asm volatile("cp.async.commit_group;" ::: "memory");
}
__device__ __forceinline__ void cp_wait0() {
    asm volatile("cp.async.wait_group 0;" ::: "memory");
}

// ---------------------------------------------------------------------------
// Kernel 1: per-row squared norms + p = x@(W1a-W1b)+b1, q = x@W1b
// ---------------------------------------------------------------------------
__global__ __launch_bounds__(256) void pq_kernel(const float* __restrict__ x,
                                                 const float* __restrict__ W1,
                                                 const float* __restrict__ b1) {
    __shared__ float sx[8 * D];
    const int i0 = blockIdx.x * 8;
    const int t = threadIdx.x;

    for (int u = t; u < 8 * D; u += 256) sx[u] = x[i0 * D + u];
    __syncthreads();

    if (t < 8) {
        float s = 0.f;
        #pragma unroll
        for (int d = 0; d < D; d++) { float v = sx[t * D + d]; s = fmaf(v, v, s); }
        g_sq[i0 + t] = s;
    }

    float acc[8];
    #pragma unroll
    for (int m = 0; m < 8; m++) acc[m] = 0.f;

    if (t < DO) {
        const int c = t;
        for (int d = 0; d < D; d++) {
            float w = W1[d * DO + c] - W1[(D + d) * DO + c];
            #pragma unroll
            for (int m = 0; m < 8; m++) acc[m] = fmaf(sx[m * D + d], w, acc[m]);
        }
        float bb = b1[c];
        #pragma unroll
        for (int m = 0; m < 8; m++) g_p[(size_t)(i0 + m) * DO + c] = acc[m] + bb;
    } else {
        const int c = t - DO;
        for (int d = 0; d < D; d++) {
            float w = W1[(D + d) * DO + c];
            #pragma unroll
            for (int m = 0; m < 8; m++) acc[m] = fmaf(sx[m * D + d], w, acc[m]);
        }
        #pragma unroll
        for (int m = 0; m < 8; m++) g_q[(size_t)(i0 + m) * DO + c] = acc[m];
    }
}

// ---------------------------------------------------------------------------
// Kernel 2a: phase A — exact top-16 per (row, 128-j subsegment), j < 1024.
// grid = (64, 8). EXACT R11 version.
// ---------------------------------------------------------------------------
__global__ __launch_bounds__(128, 4) void knnA_kernel(const float* __restrict__ x) {
    __shared__ ulonglong2 sj[TJ * 16];
    __shared__ float ssq[TJ];
    const int tid = threadIdx.x;
    const int i = blockIdx.x * 128 + tid;
    const int s = blockIdx.y;

    ulonglong2 xi[16];
    const ulonglong2* xr = reinterpret_cast<const ulonglong2*>(x) + (size_t)i * 16;
    #pragma unroll
    for (int c = 0; c < 16; c++) xi[c] = xr[c];
    const float sqi = g_sq[i];

    float kd[K];
    int   kj[K];
    #pragma unroll
    for (int n = 0; n < K; n++) { kd[n] = 3.4e38f; kj[n] = 0; }

    const int jbeg = s * JSEGA, jend = jbeg + JSEGA;
    for (int jb = jbeg; jb < jend; jb += TJ) {
        const ulonglong2* gs = reinterpret_cast<const ulonglong2*>(x) + (size_t)jb * 16;
        #pragma unroll
        for (int u = tid; u < TJ * 16; u += 128) sj[u] = gs[u];
        if (tid < TJ) ssq[tid] = g_sq[jb + tid];
        __syncthreads();

        #pragma unroll 2
        for (int jj = 0; jj < TJ; jj++) {
            u64 a0 = 0ull, a1 = 0ull, a2 = 0ull, a3 = 0ull;
            #pragma unroll
            for (int c = 0; c < 16; c += 2) {
                ulonglong2 v0 = sj[jj * 16 + c];
                ulonglong2 v1 = sj[jj * 16 + c + 1];
                a0 = ffma2(xi[c].x, v0.x, a0);
                a1 = ffma2(xi[c].y, v0.y, a1);
                a2 = ffma2(xi[c + 1].x, v1.x, a2);
                a3 = ffma2(xi[c + 1].y, v1.y, a3);
            }
            u64 st = fadd2(fadd2(a0, a1), fadd2(a2, a3));
            unsigned lo, hi;
            asm("mov.b64 {%0, %1}, %2;" : "=r"(lo), "=r"(hi) : "l"(st));
            float dot = __uint_as_float(lo) + __uint_as_float(hi);
            float dist = fmaf(-2.f, dot, sqi + ssq[jj]);
            if (dist < kd[K - 1]) {
                kd[K - 1] = dist; kj[K - 1] = jb + jj;
                #pragma unroll
                for (int n = K - 1; n > 0; n--) {
                    if (kd[n] < kd[n - 1]) {
                        float td = kd[n]; kd[n] = kd[n - 1]; kd[n - 1] = td;
                        int   tj = kj[n]; kj[n] = kj[n - 1]; kj[n - 1] = tj;
                    }
                }
            }
        }
        __syncthreads();
    }

    u64* dst = g_ck + ((size_t)i * SEGA + s) * K;
    #pragma unroll
    for (int n = 0; n < K; n++)
        dst[n] = ((u64)fkey(kd[n]) << 32) | (unsigned)kj[n];
}

// ---------------------------------------------------------------------------
// Kernel 2b: threshold — exact 16th-smallest key of each row's 128 A-keys.
// EXACT R11 version (thread per row).
// ---------------------------------------------------------------------------
__global__ __launch_bounds__(128) void thresh_kernel() {
    const int i = blockIdx.x * 128 + threadIdx.x;
    const u64* src = g_ck + (size_t)i * SEGA * K;

    u64 kd[K];
    #pragma unroll
    for (int n = 0; n < K; n++) kd[n] = 0xFFFFFFFFFFFFFFFFull;

    for (int u = 0; u < SEGA * K; u++) {
        u64 e = src[u];
        if (e < kd[K - 1]) {
            kd[K - 1] = e;
            #pragma unroll
            for (int n = K - 1; n > 0; n--) {
                if (kd[n] < kd[n - 1]) { u64 tm = kd[n]; kd[n] = kd[n - 1]; kd[n - 1] = tm; }
                else break;
            }
        }
    }
    g_thr[i] = unfkey((u32)(kd[K - 1] >> 32));
}

// ---------------------------------------------------------------------------
// Kernel 2c: phase B — fixed-threshold scan, j in [1024, 8192), 2 rows/thread,
// cp.async DOUBLE-BUFFERED tile staging (hot math identical to R11).
// grid = (32, 14), block 128.
// ---------------------------------------------------------------------------
__global__ __launch_bounds__(128, 2) void knnB_kernel(const float* __restrict__ x) {
    __shared__ ulonglong2 sj[2][TJ * 16];
    __shared__ float ssq[2][TJ];
    __shared__ float sd[16 * 132];
    const int tid = threadIdx.x;
    const int iA = blockIdx.x * 256 + tid;
    const int iB = iA + 128;
    const int s = blockIdx.y;

    ulonglong2 xa[16], xb[16];
    const ulonglong2* ra = reinterpret_cast<const ulonglong2*>(x) + (size_t)iA * 16;
    const ulonglong2* rb = reinterpret_cast<const ulonglong2*>(x) + (size_t)iB * 16;
    #pragma unroll
    for (int c = 0; c < 16; c++) { xa[c] = ra[c]; xb[c] = rb[c]; }
    const float sqa = g_sq[iA], sqb = g_sq[iB];
    const float tha = g_thr[iA], thb = g_thr[iB];

    u64* cpa = g_cand + ((size_t)iA * SEGB + s) * CAP;
    u64* cpb = g_cand + ((size_t)iB * SEGB + s) * CAP;
    int ca = 0, cb = 0;

    const int jbeg = JB0 + s * JSEGB;

    // Stage tile 0 asynchronously.
    {
        const ulonglong2* gs = reinterpret_cast<const ulonglong2*>(x) + (size_t)jbeg * 16;
        u32 base = (u32)__cvta_generic_to_shared(&sj[0][0]);
        #pragma unroll
        for (int r = 0; r < 8; r++)
            cp16(base + (tid + r * 128) * 16, gs + tid + r * 128);
        if (tid < TJ)
            cp4((u32)__cvta_generic_to_shared(&ssq[0][tid]), &g_sq[jbeg + tid]);
        cp_commit();
    }
    cp_wait0();
    __syncthreads();

    for (int tt = 0; tt < NTB; tt++) {
        const int buf = tt & 1;
        const int jb = jbeg + tt * TJ;

        // Issue async copy for the NEXT tile (fire and forget).
        if (tt + 1 < NTB) {
            const int jn = jb + TJ;
            const ulonglong2* gs = reinterpret_cast<const ulonglong2*>(x) + (size_t)jn * 16;
            u32 base = (u32)__cvta_generic_to_shared(&sj[buf ^ 1][0]);
            #pragma unroll
            for (int r = 0; r < 8; r++)
                cp16(base + (tid + r * 128) * 16, gs + tid + r * 128);
            if (tid < TJ)
                cp4((u32)__cvta_generic_to_shared(&ssq[buf ^ 1][tid]), &g_sq[jn + tid]);
            cp_commit();
        }

        // Compute on current buffer (identical to R11 hot loop).
        #pragma unroll 1
        for (int c8 = 0; c8 < TJ / 8; c8++) {
            u32 ma = 0, mb = 0;
            #pragma unroll 2
            for (int u = 0; u < 8; u++) {
                const int jj = c8 * 8 + u;
                u64 a0 = 0ull, a1 = 0ull, a2 = 0ull, a3 = 0ull;
                u64 b0 = 0ull, b1 = 0ull, b2 = 0ull, b3 = 0ull;
                #pragma unroll
                for (int c = 0; c < 16; c += 2) {
                    ulonglong2 v0 = sj[buf][jj * 16 + c];
                    ulonglong2 v1 = sj[buf][jj * 16 + c + 1];
                    a0 = ffma2(xa[c].x, v0.x, a0);
                    a1 = ffma2(xa[c].y, v0.y, a1);
                    a2 = ffma2(xa[c + 1].x, v1.x, a2);
                    a3 = ffma2(xa[c + 1].y, v1.y, a3);
                    b0 = ffma2(xb[c].x, v0.x, b0);
                    b1 = ffma2(xb[c].y, v0.y, b1);
                    b2 = ffma2(xb[c + 1].x, v1.x, b2);
                    b3 = ffma2(xb[c + 1].y, v1.y, b3);
                }
                const float sjv = ssq[buf][jj];
                u64 sta = fadd2(fadd2(a0, a1), fadd2(a2, a3));
                u64 stb = fadd2(fadd2(b0, b1), fadd2(b2, b3));
                unsigned lo, hi;
                asm("mov.b64 {%0, %1}, %2;" : "=r"(lo), "=r"(hi) : "l"(sta));
                float dA = fmaf(-2.f, __uint_as_float(lo) + __uint_as_float(hi),
                                sqa + sjv);
                asm("mov.b64 {%0, %1}, %2;" : "=r"(lo), "=r"(hi) : "l"(stb));
                float dB = fmaf(-2.f, __uint_as_float(lo) + __uint_as_float(hi),
                                sqb + sjv);
                sd[u * 132 + tid] = dA;
                sd[(8 + u) * 132 + tid] = dB;
                ma |= (dA <= tha) ? (1u << u) : 0u;
                mb |= (dB <= thb) ? (1u << u) : 0u;
            }
            // Drain (rare).
            while (ma) {
                int b = __ffs(ma) - 1;
                ma &= ma - 1;
                float dv = sd[b * 132 + tid];
                int jv = jb + c8 * 8 + b;
                int slot = (ca < CAP) ? ca : (CAP - 1);
                cpa[slot] = ((u64)fkey(dv) << 32) | (u32)jv;
                ca++;
            }
            while (mb) {
                int b = __ffs(mb) - 1;
                mb &= mb - 1;
                float dv = sd[(8 + b) * 132 + tid];
                int jv = jb + c8 * 8 + b;
                int slot = (cb < CAP) ? cb : (CAP - 1);
                cpb[slot] = ((u64)fkey(dv) << 32) | (u32)jv;
                cb++;
            }
        }

        // Next tile's copy must have landed before anyone reads it.
        cp_wait0();
        __syncthreads();
    }

    g_cnt[iA * SEGB + s] = (ca < CAP) ? ca : CAP;
    g_cnt[iB * SEGB + s] = (cb < CAP) ? cb : CAP;
}

// ---------------------------------------------------------------------------
// Kernel 3: merge — warp per row over 128 A-keys + appended B-keys;
// per-lane sorted top-16, then 16-round warp-min extraction. EXACT R11.
// ---------------------------------------------------------------------------
__global__ __launch_bounds__(256) void merge_kernel() {
    const int t = threadIdx.x;
    const int w = t >> 5, lane = t & 31;
    const int i = blockIdx.x * 8 + w;

    u64 kd[K];
    #pragma unroll
    for (int n = 0; n < K; n++) kd[n] = 0xFFFFFFFFFFFFFFFFull;

    const u64* ak = g_ck + (size_t)i * SEGA * K;
    for (int u = lane; u < SEGA * K; u += 32) {
        u64 e = ak[u];
        if (e < kd[K - 1]) {
            kd[K - 1] = e;
            #pragma unroll
            for (int n = K - 1; n > 0; n--) {
                if (kd[n] < kd[n - 1]) { u64 tm = kd[n]; kd[n] = kd[n - 1]; kd[n - 1] = tm; }
                else break;
            }
        }
    }
    for (int s = 0; s < SEGB; s++) {
        const int c = g_cnt[i * SEGB + s];
        const u64* p = g_cand + ((size_t)i * SEGB + s) * CAP;
        for (int u = lane; u < c; u += 32) {
            u64 e = p[u];
            if (e < kd[K - 1]) {
                kd[K - 1] = e;
                #pragma unroll
                for (int n = K - 1; n > 0; n--) {
                    if (kd[n] < kd[n - 1]) { u64 tm = kd[n]; kd[n] = kd[n - 1]; kd[n - 1] = tm; }
                    else break;
                }
            }
        }
    }

    for (int r = 0; r < K; r++) {
        u64 h = kd[0];
        u64 m = h;
        #pragma unroll
        for (int off = 16; off > 0; off >>= 1) {
            u64 o = __shfl_down_sync(0xFFFFFFFFu, m, off);
            if (o < m) m = o;
        }
        m = __shfl_sync(0xFFFFFFFFu, m, 0);
        if (h == m) {
            g_nbr[(size_t)i * K + r] = (int)(m & 0xFFFFFFFFull);
            #pragma unroll
            for (int c = 0; c < K - 1; c++) kd[c] = kd[c + 1];
            kd[K - 1] = 0xFFFFFFFFFFFFFFFFull;
        }
    }
}

// ---------------------------------------------------------------------------
// Kernel 4: aggregate r = mean_n relu(p_i + q_jn), out = r@W2 + b2. EXACT R11.
// ---------------------------------------------------------------------------
__global__ __launch_bounds__(128) void agg_kernel(const float* __restrict__ W2,
                                                  const float* __restrict__ b2,
                                                  float* __restrict__ out) {
    __shared__ int snbr[K];
    __shared__ float sr[DO];
    const int i = blockIdx.x;
    const int t = threadIdx.x;

    if (t < K) snbr[t] = g_nbr[(size_t)i * K + t];
    __syncthreads();

    float p = g_p[(size_t)i * DO + t];
    float acc = 0.f;
    #pragma unroll
    for (int n = 0; n < K; n++) {
        int j = snbr[n];
        acc += fmaxf(p + g_q[(size_t)j * DO + t], 0.f);
    }
    sr[t] = acc * (1.f / K);
    __syncthreads();

    float o = b2[t];
    #pragma unroll 8
    for (int d = 0; d < DO; d++)
        o = fmaf(sr[d], W2[d * DO + t], o);
    out[(size_t)i * DO + t] = o;
}

// ---------------------------------------------------------------------------
extern "C" void kernel_launch(void* const* d_in, const int* in_sizes, int n_in,
                              void* d_out, int out_size) {
    const float* x  = (const float*)d_in[0];
    const float* W1 = (const float*)d_in[1];
    const float* b1 = (const float*)d_in[2];
    const float* W2 = (const float*)d_in[3];
    const float* b2 = (const float*)d_in[4];
    float* out = (float*)d_out;

    pq_kernel<<<NN / 8, 256>>>(x, W1, b1);
    knnA_kernel<<<dim3(NN / 128, SEGA), 128>>>(x);
    thresh_kernel<<<NN / 128, 128>>>();
    knnB_kernel<<<dim3(NN / 256, SEGB), 128>>>(x);
    merge_kernel<<<NN / 8, 256>>>();
    agg_kernel<<<NN, 128>>>(W2, b2, out);
}